// round 4
// baseline (speedup 1.0000x reference)
#include <cuda_runtime.h>
#include <cuda_fp16.h>
#include <stdint.h>

#define B_TOT   16384
#define N_IN    6
#define N_MF    5
#define N_FUZZ  30
#define N_RULES 2048
#define NSPLIT  32
#define RPS     (N_RULES / NSPLIT)   // 64 rules per split
#define TPB     128
#define EPB     512                  // batch elems per block (4 per thread)
#define NGROUP  (B_TOT / EPB)        // 32
#define EPS_F   1e-12f

// Scratch (__device__ globals: no allocation allowed)
__device__ __half  g_fuzz[N_FUZZ * B_TOT];     // [idx][b], 983 KB
__device__ float4  g_partial[NSPLIT * B_TOT];  // {l1, d0, d1, pad}
__device__ int     g_cnt[NGROUP];              // zero-init; reset after use

// ---- packed f32x2 helpers (Blackwell FFMA2 path; ptxas won't auto-fuse) ----
typedef unsigned long long u64;
static __device__ __forceinline__ u64 pack2(float lo, float hi) {
    u64 r; asm("mov.b64 %0, {%1, %2};" : "=l"(r) : "f"(lo), "f"(hi)); return r;
}
static __device__ __forceinline__ void unpack2(float& lo, float& hi, u64 v) {
    asm("mov.b64 {%0, %1}, %2;" : "=f"(lo), "=f"(hi) : "l"(v));
}
static __device__ __forceinline__ u64 add2(u64 a, u64 b) {
    u64 r; asm("add.rn.f32x2 %0, %1, %2;" : "=l"(r) : "l"(a), "l"(b)); return r;
}
static __device__ __forceinline__ u64 fma2(u64 a, u64 b, u64 c) {
    u64 r; asm("fma.rn.f32x2 %0, %1, %2, %3;" : "=l"(r) : "l"(a), "l"(b), "l"(c)); return r;
}

// ---------------------------------------------------------------------------
// Kernel 1: fuzzify once. g_fuzz[idx][b] as half.
// ---------------------------------------------------------------------------
__global__ __launch_bounds__(256) void fuzz_kernel(
    const float* __restrict__ x,
    const float* __restrict__ mf_centers,
    const float* __restrict__ mf_scales) {
    int b = blockIdx.x * 256 + threadIdx.x;
    float xv[N_IN];
    #pragma unroll
    for (int i = 0; i < N_IN; i++) xv[i] = x[b * N_IN + i];
    #pragma unroll
    for (int i = 0; i < N_IN; i++) {
        #pragma unroll
        for (int j = 0; j < N_MF; j++) {
            float c = __ldg(&mf_centers[i * N_MF + j]);
            float s = __ldg(&mf_scales[i * N_MF + j]);
            float z = __fdividef(xv[i] - c, s);
            g_fuzz[(i * N_MF + j) * B_TOT + b] = __float2half_rn(__expf(-z * z));
        }
    }
}

// ---------------------------------------------------------------------------
// Kernel 2: fused rule-eval + finalize.
//  - SMEM fuzz word (idx, tid) = uint2 {half2(e0,e1), half2(e2,e3)}; one
//    LDS.64 gather serves 4 batch elems; conflict-free (lane phase covers
//    all 32 banks; idx offset is a multiple of 128B).
//  - __launch_bounds__(128, 6): cap regs at ~85 so 6 blocks/SM co-reside
//    (SMEM 33KB x 6 = 198KB <= 228KB) -> 24 warps/SM for LDS latency hiding.
//  - unroll 2 to keep live ranges small under the reg cap.
// ---------------------------------------------------------------------------
__global__ __launch_bounds__(TPB, 6) void anfis_main_kernel(
    const float* __restrict__ out_centers,
    const int*   __restrict__ input_rules,
    const int*   __restrict__ output_rules,
    float* __restrict__ out)
{
    __shared__ uint2      s_fuzz[N_FUZZ * TPB];  // 30 KB
    __shared__ uint4      s_pk[RPS];             // 1 KB
    __shared__ ulonglong2 s_owd[RPS];            // 1 KB
    __shared__ int        s_flag;

    const int tid   = threadIdx.x;
    const int grp   = blockIdx.x;
    const int split = blockIdx.y;
    const int base  = grp * EPB;

    // ---- pack this split's rules ----
    if (tid < RPS) {
        const int r = split * RPS + tid;
        const int* ir = input_rules + r * N_IN;
        unsigned p0 = (unsigned)ir[0] << 10;   // idx * 1024B row stride
        unsigned p1 = (unsigned)ir[1] << 10;
        unsigned p2 = (unsigned)ir[2] << 10;
        unsigned p3 = (unsigned)ir[3] << 10;
        unsigned p4 = (unsigned)ir[4] << 10;
        unsigned p5 = (unsigned)ir[5] << 10;
        float ow0 = out_centers[output_rules[r * 2 + 0]];
        float ow1 = out_centers[output_rules[r * 2 + 1]];
        s_pk[tid]  = make_uint4(p0 | (p1 << 16), p2 | (p3 << 16), p4 | (p5 << 16), 0u);
        s_owd[tid] = make_ulonglong2(pack2(ow0, ow0), pack2(ow1, ow1));
    }

    // ---- stage fuzz slice: coalesced LDG.64 ----
    {
        const uint2* gsrc = reinterpret_cast<const uint2*>(g_fuzz) + grp * TPB + tid;
        #pragma unroll
        for (int idx = 0; idx < N_FUZZ; idx++)
            s_fuzz[idx * TPB + tid] = gsrc[idx * (B_TOT / 4)];
    }
    __syncthreads();

    // ---- rule loop ----
    const char* fb = reinterpret_cast<const char*>(s_fuzz) + tid * 8;
    u64 l1A = 0, d0A = 0, d1A = 0;   // elems e0,e1
    u64 l1B = 0, d0B = 0, d1B = 0;   // elems e2,e3

    #pragma unroll 2
    for (int k = 0; k < RPS; k++) {
        const uint4      pk = s_pk[k];     // LDS.128 broadcast
        const ulonglong2 ow = s_owd[k];    // LDS.128 broadcast

        uint2 f0 = *reinterpret_cast<const uint2*>(fb + (pk.x & 0xFFFFu));
        uint2 f1 = *reinterpret_cast<const uint2*>(fb + (pk.x >> 16));
        __half2 mA = __hmin2(*(__half2*)&f0.x, *(__half2*)&f1.x);
        __half2 mB = __hmin2(*(__half2*)&f0.y, *(__half2*)&f1.y);
        uint2 f2 = *reinterpret_cast<const uint2*>(fb + (pk.y & 0xFFFFu));
        uint2 f3 = *reinterpret_cast<const uint2*>(fb + (pk.y >> 16));
        mA = __hmin2(mA, __hmin2(*(__half2*)&f2.x, *(__half2*)&f3.x));
        mB = __hmin2(mB, __hmin2(*(__half2*)&f2.y, *(__half2*)&f3.y));
        uint2 f4 = *reinterpret_cast<const uint2*>(fb + (pk.z & 0xFFFFu));
        uint2 f5 = *reinterpret_cast<const uint2*>(fb + (pk.z >> 16));
        mA = __hmin2(mA, __hmin2(*(__half2*)&f4.x, *(__half2*)&f5.x));
        mB = __hmin2(mB, __hmin2(*(__half2*)&f4.y, *(__half2*)&f5.y));

        u64 wA = pack2(__low2float(mA), __high2float(mA));
        u64 wB = pack2(__low2float(mB), __high2float(mB));

        l1A = add2(l1A, wA);            l1B = add2(l1B, wB);
        d0A = fma2(wA, ow.x, d0A);      d0B = fma2(wB, ow.x, d0B);
        d1A = fma2(wA, ow.y, d1A);      d1B = fma2(wB, ow.y, d1B);
    }

    // ---- write partials (4 consecutive float4 = 64B coalesced) ----
    {
        float l0, l1, d00, d01, d10, d11;
        float4* p = &g_partial[split * B_TOT + base + 4 * tid];
        unpack2(l0, l1, l1A); unpack2(d00, d01, d0A); unpack2(d10, d11, d1A);
        p[0] = make_float4(l0, d00, d10, 0.f);
        p[1] = make_float4(l1, d01, d11, 0.f);
        unpack2(l0, l1, l1B); unpack2(d00, d01, d0B); unpack2(d10, d11, d1B);
        p[2] = make_float4(l0, d00, d10, 0.f);
        p[3] = make_float4(l1, d01, d11, 0.f);
    }

    // ---- last-block finalize (deterministic fixed-order summation) ----
    __threadfence();
    __syncthreads();
    if (tid == 0) {
        int old = atomicAdd(&g_cnt[grp], 1);
        s_flag = (old == NSPLIT - 1);
    }
    __syncthreads();

    if (s_flag) {
        __threadfence();
        #pragma unroll
        for (int e = 0; e < 4; e++) {
            const int b = base + 4 * tid + e;
            float l1 = 0.f, d0 = 0.f, d1 = 0.f;
            #pragma unroll
            for (int s = 0; s < NSPLIT; s++) {
                float4 p = __ldcg(&g_partial[s * B_TOT + b]);
                l1 += p.x; d0 += p.y; d1 += p.z;
            }
            float inv = __fdividef(1.0f, fmaxf(l1, EPS_F));
            float o0 = tanhf(d0 * inv) * 4.0f;            // scale 4.0, center 0.0
            float o1 = tanhf(d1 * inv) * 0.75f + 0.75f;   // scale .75, center .75
            reinterpret_cast<float2*>(out)[b] = make_float2(o0, o1);
        }
        if (tid == 0) g_cnt[grp] = 0;   // reset for next graph replay
    }
}

// ---------------------------------------------------------------------------
extern "C" void kernel_launch(void* const* d_in, const int* in_sizes, int n_in,
                              void* d_out, int out_size) {
    const float* x            = (const float*)d_in[0];
    const float* mf_centers   = (const float*)d_in[1];
    const float* mf_scales    = (const float*)d_in[2];
    const float* out_centers  = (const float*)d_in[3];
    const int*   input_rules  = (const int*)d_in[4];
    const int*   output_rules = (const int*)d_in[5];

    fuzz_kernel<<<B_TOT / 256, 256>>>(x, mf_centers, mf_scales);

    dim3 grid(NGROUP, NSPLIT);
    anfis_main_kernel<<<grid, TPB>>>(out_centers, input_rules, output_rules,
                                     (float*)d_out);
}

// round 5
// speedup vs baseline: 1.2510x; 1.2510x over previous
#include <cuda_runtime.h>
#include <cuda_fp16.h>
#include <stdint.h>

#define B_TOT   16384
#define N_IN    6
#define N_MF    5
#define N_FUZZ  30
#define N_RULES 2048
#define NSPLIT  16
#define RPS     (N_RULES / NSPLIT)   // 128 rules per split
#define TPB     128
#define EPB     256                  // batch elems per block (2 per thread, half2)
#define NGROUP  (B_TOT / EPB)        // 64
#define EPS_F   1e-12f

// Scratch (__device__ globals: no allocation allowed)
__device__ float4 g_partial[NSPLIT * B_TOT];   // {l1, d0, d1, pad}
__device__ int    g_cnt[NGROUP];               // zero-init; reset after use

// ---- packed f32x2 helpers (Blackwell; ptxas won't auto-fuse) ----
typedef unsigned long long u64;
static __device__ __forceinline__ u64 pack2(float lo, float hi) {
    u64 r; asm("mov.b64 %0, {%1, %2};" : "=l"(r) : "f"(lo), "f"(hi)); return r;
}
static __device__ __forceinline__ void unpack2(float& lo, float& hi, u64 v) {
    asm("mov.b64 {%0, %1}, %2;" : "=f"(lo), "=f"(hi) : "l"(v));
}
static __device__ __forceinline__ u64 add2(u64 a, u64 b) {
    u64 r; asm("add.rn.f32x2 %0, %1, %2;" : "=l"(r) : "l"(a), "l"(b)); return r;
}
static __device__ __forceinline__ u64 fma2(u64 a, u64 b, u64 c) {
    u64 r; asm("fma.rn.f32x2 %0, %1, %2, %3;" : "=l"(r) : "l"(a), "l"(b), "l"(c)); return r;
}

// ---------------------------------------------------------------------------
// Single fused kernel (R2 structure; grid doubled, f32x2 accumulation).
//  - grid = (NGROUP=64, NSPLIT=16) = 1024 blocks -> ~6.9 blocks/SM,
//    ~28 warps/SM to hide the lat-29 LDS chain (R2 was grid-starved at 512).
//  - Fuzz table in SMEM as half2 {fuzz[b0], fuzz[b1]}, b1 = b0+128. One
//    LDS.32 gather serves both elems; bank = tid mod 32 -> conflict-free.
//  - Rules pre-packed: uint4 of 6 x 16-bit byte offsets (idx*512B), plus
//    ulonglong2 {pack(ow0,ow0), pack(ow1,ow1)} for packed-f32x2 FMA.
//  - Last-arriving split block per group finalizes (deterministic order).
// ---------------------------------------------------------------------------
__global__ __launch_bounds__(TPB) void anfis_fused_kernel(
    const float* __restrict__ x,
    const float* __restrict__ mf_centers,
    const float* __restrict__ mf_scales,
    const float* __restrict__ out_centers,
    const int*   __restrict__ input_rules,
    const int*   __restrict__ output_rules,
    float* __restrict__ out)
{
    __shared__ __half2    s_fuzz[N_FUZZ * TPB];  // 15 KB
    __shared__ uint4      s_pk[RPS];             // 2 KB
    __shared__ ulonglong2 s_owd[RPS];            // 2 KB
    __shared__ int        s_flag;

    const int tid   = threadIdx.x;
    const int grp   = blockIdx.x;
    const int split = blockIdx.y;
    const int b0    = grp * EPB + tid;
    const int b1    = b0 + TPB;

    // ---- pack this split's rules into SMEM ----
    if (tid < RPS) {
        const int r = split * RPS + tid;
        const int* ir = input_rules + r * N_IN;
        unsigned p0 = (unsigned)ir[0] << 9;   // idx * 512B row stride (<= 14848)
        unsigned p1 = (unsigned)ir[1] << 9;
        unsigned p2 = (unsigned)ir[2] << 9;
        unsigned p3 = (unsigned)ir[3] << 9;
        unsigned p4 = (unsigned)ir[4] << 9;
        unsigned p5 = (unsigned)ir[5] << 9;
        float ow0 = out_centers[output_rules[r * 2 + 0]];
        float ow1 = out_centers[output_rules[r * 2 + 1]];
        s_pk[tid]  = make_uint4(p0 | (p1 << 16), p2 | (p3 << 16), p4 | (p5 << 16), 0u);
        s_owd[tid] = make_ulonglong2(pack2(ow0, ow0), pack2(ow1, ow1));
    }

    // ---- fuzzify both batch elems, store as half2 pairs ----
    {
        float xa[N_IN], xb[N_IN];
        #pragma unroll
        for (int i = 0; i < N_IN; i++) {
            xa[i] = x[b0 * N_IN + i];
            xb[i] = x[b1 * N_IN + i];
        }
        #pragma unroll
        for (int i = 0; i < N_IN; i++) {
            #pragma unroll
            for (int j = 0; j < N_MF; j++) {
                float c  = __ldg(&mf_centers[i * N_MF + j]);
                float s  = __ldg(&mf_scales[i * N_MF + j]);
                float za = __fdividef(xa[i] - c, s);
                float zb = __fdividef(xb[i] - c, s);
                s_fuzz[(i * N_MF + j) * TPB + tid] =
                    __floats2half2_rn(__expf(-za * za), __expf(-zb * zb));
            }
        }
    }
    __syncthreads();

    // ---- rule loop: 6 LDS.32 gathers, packed min, packed f32x2 accum ----
    const char* fb = reinterpret_cast<const char*>(s_fuzz) + tid * 4;
    u64 l1 = 0, d0 = 0, d1 = 0;

    #pragma unroll 4
    for (int k = 0; k < RPS; k++) {
        const uint4      pk = s_pk[k];     // LDS.128 broadcast
        const ulonglong2 ow = s_owd[k];    // LDS.128 broadcast

        __half2 f0 = *reinterpret_cast<const __half2*>(fb + (pk.x & 0xFFFFu));
        __half2 f1 = *reinterpret_cast<const __half2*>(fb + (pk.x >> 16));
        __half2 f2 = *reinterpret_cast<const __half2*>(fb + (pk.y & 0xFFFFu));
        __half2 f3 = *reinterpret_cast<const __half2*>(fb + (pk.y >> 16));
        __half2 f4 = *reinterpret_cast<const __half2*>(fb + (pk.z & 0xFFFFu));
        __half2 f5 = *reinterpret_cast<const __half2*>(fb + (pk.z >> 16));

        __half2 w = __hmin2(__hmin2(__hmin2(f0, f1), __hmin2(f2, f3)),
                            __hmin2(f4, f5));

        u64 wp = pack2(__low2float(w), __high2float(w));
        l1 = add2(l1, wp);              // weights >= 0
        d0 = fma2(wp, ow.x, d0);
        d1 = fma2(wp, ow.y, d1);
    }

    // ---- write partials ----
    {
        float la, lb, d0a, d0b, d1a, d1b;
        unpack2(la, lb, l1); unpack2(d0a, d0b, d0); unpack2(d1a, d1b, d1);
        g_partial[split * B_TOT + b0] = make_float4(la, d0a, d1a, 0.f);
        g_partial[split * B_TOT + b1] = make_float4(lb, d0b, d1b, 0.f);
    }

    // ---- last-block finalize (deterministic fixed-order summation) ----
    __threadfence();
    __syncthreads();
    if (tid == 0) {
        int old = atomicAdd(&g_cnt[grp], 1);
        s_flag = (old == NSPLIT - 1);
    }
    __syncthreads();

    if (s_flag) {
        __threadfence();
        #pragma unroll
        for (int e = 0; e < 2; e++) {
            const int b = (e == 0) ? b0 : b1;
            float l = 0.f, s0 = 0.f, s1 = 0.f;
            #pragma unroll
            for (int s = 0; s < NSPLIT; s++) {
                float4 p = __ldcg(&g_partial[s * B_TOT + b]);
                l += p.x; s0 += p.y; s1 += p.z;
            }
            float inv = __fdividef(1.0f, fmaxf(l, EPS_F));
            float o0 = tanhf(s0 * inv) * 4.0f;            // scale 4.0, center 0.0
            float o1 = tanhf(s1 * inv) * 0.75f + 0.75f;   // scale .75, center .75
            reinterpret_cast<float2*>(out)[b] = make_float2(o0, o1);
        }
        if (tid == 0) g_cnt[grp] = 0;   // reset for next graph replay
    }
}

// ---------------------------------------------------------------------------
extern "C" void kernel_launch(void* const* d_in, const int* in_sizes, int n_in,
                              void* d_out, int out_size) {
    const float* x            = (const float*)d_in[0];
    const float* mf_centers   = (const float*)d_in[1];
    const float* mf_scales    = (const float*)d_in[2];
    const float* out_centers  = (const float*)d_in[3];
    const int*   input_rules  = (const int*)d_in[4];
    const int*   output_rules = (const int*)d_in[5];

    dim3 grid(NGROUP, NSPLIT);
    anfis_fused_kernel<<<grid, TPB>>>(x, mf_centers, mf_scales, out_centers,
                                      input_rules, output_rules, (float*)d_out);
}

// round 6
// speedup vs baseline: 1.3395x; 1.0707x over previous
#include <cuda_runtime.h>
#include <cuda_fp16.h>
#include <stdint.h>

#define B_TOT   16384
#define N_IN    6
#define N_MF    5
#define N_FUZZ  30
#define N_RULES 2048
#define NSPLIT  16
#define RPS     (N_RULES / NSPLIT)   // 128 rules per split
#define TPB     128
#define EPB     256                  // batch elems per block (2 per thread, half2)
#define NGROUP  (B_TOT / EPB)        // 64
#define EPS_F   1e-12f
#define SQRT_LOG2E 1.2011224087864498f   // sqrt(log2(e))

// Scratch (__device__ globals: no allocation allowed)
__device__ float4 g_partial[NSPLIT * B_TOT];   // {l1, d0, d1, pad}
__device__ int    g_cnt[NGROUP];               // zero-init; reset after use

// ---- packed f32x2 helpers ----
typedef unsigned long long u64;
static __device__ __forceinline__ u64 pack2(float lo, float hi) {
    u64 r; asm("mov.b64 %0, {%1, %2};" : "=l"(r) : "f"(lo), "f"(hi)); return r;
}
static __device__ __forceinline__ void unpack2(float& lo, float& hi, u64 v) {
    asm("mov.b64 {%0, %1}, %2;" : "=f"(lo), "=f"(hi) : "l"(v));
}
static __device__ __forceinline__ u64 add2(u64 a, u64 b) {
    u64 r; asm("add.rn.f32x2 %0, %1, %2;" : "=l"(r) : "l"(a), "l"(b)); return r;
}
static __device__ __forceinline__ u64 fma2(u64 a, u64 b, u64 c) {
    u64 r; asm("fma.rn.f32x2 %0, %1, %2, %3;" : "=l"(r) : "l"(a), "l"(b), "l"(c)); return r;
}
static __device__ __forceinline__ float ex2(float v) {
    float r; asm("ex2.approx.ftz.f32 %0, %1;" : "=f"(r) : "f"(v)); return r;
}

// ---------------------------------------------------------------------------
// Single fused kernel.
//  - Fuzz table in SMEM as half2 {fuzz[b0], fuzz[b1]}, b1 = b0+128; one
//    LDS.32 gather serves 2 elems; bank = tid mod 32 -> conflict-free.
//  - Rules staged UNPACKED: 6 raw u32 byte-offsets + ow0 + ow1 as two uint4
//    -> 2 LDS.128 broadcasts per rule, ZERO extract ALU (just 6 IADD).
//  - Fuzzify via precomputed {c*a, a} (a = sqrt(log2e)/s): per Gaussian
//    1 FFMA + 1 FMUL + 1 ex2.approx. No per-thread RCP.
//  - Last-arriving split block per group finalizes (deterministic order).
// ---------------------------------------------------------------------------
__global__ __launch_bounds__(TPB) void anfis_fused_kernel(
    const float* __restrict__ x,
    const float* __restrict__ mf_centers,
    const float* __restrict__ mf_scales,
    const float* __restrict__ out_centers,
    const int*   __restrict__ input_rules,
    const int*   __restrict__ output_rules,
    float* __restrict__ out)
{
    __shared__ __half2 s_fuzz[N_FUZZ * TPB];  // 15 KB
    __shared__ uint4   s_pkA[RPS];            // 2 KB: off0..off3
    __shared__ uint4   s_pkB[RPS];            // 2 KB: off4, off5, ow0, ow1
    __shared__ float2  s_cs[N_FUZZ];          // {c*a, a}
    __shared__ int     s_flag;

    const int tid   = threadIdx.x;
    const int grp   = blockIdx.x;
    const int split = blockIdx.y;
    const int b0    = grp * EPB + tid;
    const int b1    = b0 + TPB;

    // ---- stage this split's rules (unpacked offsets) ----
    if (tid < RPS) {
        const int r = split * RPS + tid;
        const int* ir = input_rules + r * N_IN;
        float ow0 = out_centers[output_rules[r * 2 + 0]];
        float ow1 = out_centers[output_rules[r * 2 + 1]];
        s_pkA[tid] = make_uint4((unsigned)ir[0] << 9, (unsigned)ir[1] << 9,
                                (unsigned)ir[2] << 9, (unsigned)ir[3] << 9);
        s_pkB[tid] = make_uint4((unsigned)ir[4] << 9, (unsigned)ir[5] << 9,
                                __float_as_uint(ow0), __float_as_uint(ow1));
    }
    // ---- membership-function constants: a = sqrt(log2e)/s, b = c*a ----
    if (tid < N_FUZZ) {
        float c = mf_centers[tid];
        float s = mf_scales[tid];
        float a = __fdividef(SQRT_LOG2E, s);
        s_cs[tid] = make_float2(c * a, a);
    }
    __syncthreads();

    // ---- fuzzify both batch elems: exp(-z^2) = ex2(-(x*a - c*a)^2) ----
    {
        float xa[N_IN], xb[N_IN];
        #pragma unroll
        for (int i = 0; i < N_IN; i++) {
            xa[i] = x[b0 * N_IN + i];
            xb[i] = x[b1 * N_IN + i];
        }
        #pragma unroll
        for (int i = 0; i < N_IN; i++) {
            #pragma unroll
            for (int j = 0; j < N_MF; j++) {
                float2 cs = s_cs[i * N_MF + j];      // LDS.64 broadcast
                float ta = fmaf(xa[i], cs.y, -cs.x);
                float tb = fmaf(xb[i], cs.y, -cs.x);
                s_fuzz[(i * N_MF + j) * TPB + tid] =
                    __floats2half2_rn(ex2(-ta * ta), ex2(-tb * tb));
            }
        }
    }
    __syncthreads();

    // ---- rule loop: 6 LDS.32 gathers + 2 LDS.128 broadcasts per rule ----
    const char* fb = reinterpret_cast<const char*>(s_fuzz) + tid * 4;
    u64 l1 = 0, d0 = 0, d1 = 0;

    #pragma unroll 4
    for (int k = 0; k < RPS; k++) {
        const uint4 pa = s_pkA[k];     // LDS.128 broadcast
        const uint4 pb = s_pkB[k];     // LDS.128 broadcast

        __half2 f0 = *reinterpret_cast<const __half2*>(fb + pa.x);
        __half2 f1 = *reinterpret_cast<const __half2*>(fb + pa.y);
        __half2 f2 = *reinterpret_cast<const __half2*>(fb + pa.z);
        __half2 f3 = *reinterpret_cast<const __half2*>(fb + pa.w);
        __half2 f4 = *reinterpret_cast<const __half2*>(fb + pb.x);
        __half2 f5 = *reinterpret_cast<const __half2*>(fb + pb.y);

        __half2 w = __hmin2(__hmin2(__hmin2(f0, f1), __hmin2(f2, f3)),
                            __hmin2(f4, f5));

        u64 wp  = pack2(__low2float(w), __high2float(w));
        u64 ow0 = pack2(__uint_as_float(pb.z), __uint_as_float(pb.z));
        u64 ow1 = pack2(__uint_as_float(pb.w), __uint_as_float(pb.w));
        l1 = add2(l1, wp);              // weights >= 0
        d0 = fma2(wp, ow0, d0);
        d1 = fma2(wp, ow1, d1);
    }

    // ---- write partials ----
    {
        float la, lb, d0a, d0b, d1a, d1b;
        unpack2(la, lb, l1); unpack2(d0a, d0b, d0); unpack2(d1a, d1b, d1);
        g_partial[split * B_TOT + b0] = make_float4(la, d0a, d1a, 0.f);
        g_partial[split * B_TOT + b1] = make_float4(lb, d0b, d1b, 0.f);
    }

    // ---- last-block finalize (deterministic fixed-order summation) ----
    __threadfence();
    __syncthreads();
    if (tid == 0) {
        int old = atomicAdd(&g_cnt[grp], 1);
        s_flag = (old == NSPLIT - 1);
    }
    __syncthreads();

    if (s_flag) {
        __threadfence();
        #pragma unroll
        for (int e = 0; e < 2; e++) {
            const int b = (e == 0) ? b0 : b1;
            float l = 0.f, s0 = 0.f, s1 = 0.f;
            #pragma unroll
            for (int s = 0; s < NSPLIT; s++) {
                float4 p = __ldcg(&g_partial[s * B_TOT + b]);
                l += p.x; s0 += p.y; s1 += p.z;
            }
            float inv = __fdividef(1.0f, fmaxf(l, EPS_F));
            float o0 = tanhf(s0 * inv) * 4.0f;            // scale 4.0, center 0.0
            float o1 = tanhf(s1 * inv) * 0.75f + 0.75f;   // scale .75, center .75
            reinterpret_cast<float2*>(out)[b] = make_float2(o0, o1);
        }
        if (tid == 0) g_cnt[grp] = 0;   // reset for next graph replay
    }
}

// ---------------------------------------------------------------------------
extern "C" void kernel_launch(void* const* d_in, const int* in_sizes, int n_in,
                              void* d_out, int out_size) {
    const float* x            = (const float*)d_in[0];
    const float* mf_centers   = (const float*)d_in[1];
    const float* mf_scales    = (const float*)d_in[2];
    const float* out_centers  = (const float*)d_in[3];
    const int*   input_rules  = (const int*)d_in[4];
    const int*   output_rules = (const int*)d_in[5];

    dim3 grid(NGROUP, NSPLIT);
    anfis_fused_kernel<<<grid, TPB>>>(x, mf_centers, mf_scales, out_centers,
                                      input_rules, output_rules, (float*)d_out);
}